// round 10
// baseline (speedup 1.0000x reference)
#include <cuda_runtime.h>
#include <math.h>

// Problem constants (fixed by the dataset)
#define NCAP 100000
#define ECAP 1600000
#define DIM  64
#define HID  128

// ---------------- scratch (device globals; no runtime allocation) ----------
static __device__ __align__(128) int   d_cnt[NCAP];
static __device__ __align__(128) int   d_rowptr[NCAP + 1];
static __device__ __align__(128) int   d_cursor[NCAP];
static __device__ __align__(128) int   d_bsum[256];
static __device__ __align__(128) int   d_col[ECAP];
static __device__ __align__(128) float d_dinv[NCAP];
static __device__ __align__(128) float d_invdeg[NCAP];
static __device__ __align__(128) float d_x[NCAP * DIM];      // renormed entity emb
static __device__ __align__(128) float d_g[NCAP * DIM];      // relu(Ahat(x)W1+b1) @ W2

// ---------------- f32x2 packed math (Blackwell FFMA2) -----------------------
__device__ __forceinline__ unsigned long long pk2(float lo, float hi) {
    unsigned long long r;
    asm("mov.b64 %0, {%1, %2};" : "=l"(r) : "r"(__float_as_uint(lo)), "r"(__float_as_uint(hi)));
    return r;
}
__device__ __forceinline__ unsigned long long fma2(unsigned long long a,
                                                   unsigned long long b,
                                                   unsigned long long c) {
    unsigned long long d;
    asm("fma.rn.f32x2 %0, %1, %2, %3;" : "=l"(d) : "l"(a), "l"(b), "l"(c));
    return d;
}
__device__ __forceinline__ float2 upk2(unsigned long long v) {
    unsigned int lo, hi;
    asm("mov.b64 {%0, %1}, %2;" : "=r"(lo), "=r"(hi) : "l"(v));
    return make_float2(__uint_as_float(lo), __uint_as_float(hi));
}

#define NAMED_SYNC(id, cnt)   asm volatile("bar.sync %0, %1;"   :: "r"(id), "r"(cnt) : "memory")
#define NAMED_ARRIVE(id, cnt) asm volatile("bar.arrive %0, %1;" :: "r"(id), "r"(cnt) : "memory")

// ---------------- renorm entities + zero cnt (fused) -------------------------
__global__ void renorm_zero_kernel(const float* __restrict__ emb, int n) {
    int gtid = blockIdx.x * blockDim.x + threadIdx.x;
    if (gtid < n) d_cnt[gtid] = 0;
    int row = gtid >> 5;
    int lane = gtid & 31;
    if (row >= n) return;
    float2 v = *(const float2*)(emb + (size_t)row * DIM + lane * 2);
    float ss = v.x * v.x + v.y * v.y;
    #pragma unroll
    for (int o = 16; o; o >>= 1) ss += __shfl_xor_sync(0xffffffffu, ss, o);
    float nrm = sqrtf(ss);
    float sc = fminf(1.0f, 1.0f / fmaxf(nrm, 1e-12f));
    *(float2*)(d_x + (size_t)row * DIM + lane * 2) = make_float2(v.x * sc, v.y * sc);
}

// ---------------- degree counting (int4) -------------------------------------
__global__ void count_deg_kernel(const int* __restrict__ dst, int E) {
    int i = blockIdx.x * blockDim.x + threadIdx.x;
    int e = i * 4;
    if (e + 3 < E) {
        int4 d = *(const int4*)(dst + e);
        atomicAdd(&d_cnt[d.x], 1);
        atomicAdd(&d_cnt[d.y], 1);
        atomicAdd(&d_cnt[d.z], 1);
        atomicAdd(&d_cnt[d.w], 1);
    } else {
        for (; e < E; e++) atomicAdd(&d_cnt[dst[e]], 1);
    }
}

// ---------------- prefix sum (chunked) ---------------------------------------
__global__ void scan_chunk_kernel(int n) {
    __shared__ int s[1024];
    int t = threadIdx.x;
    int i = blockIdx.x * 1024 + t;
    int v = (i < n) ? d_cnt[i] : 0;
    s[t] = v;
    __syncthreads();
    for (int off = 1; off < 1024; off <<= 1) {
        int add = (t >= off) ? s[t - off] : 0;
        __syncthreads();
        s[t] += add;
        __syncthreads();
    }
    if (i < n) d_rowptr[i] = s[t] - v;   // chunk-local exclusive
    if (t == 1023) d_bsum[blockIdx.x] = s[1023];
}

// finalize with inline bsum prefix: block c adds sum(d_bsum[0..c))
__global__ void finalize_rowptr_kernel(int n, int Etot) {
    __shared__ int s_off;
    int c = blockIdx.x, t = threadIdx.x;
    if (t < 32) {
        int s = 0;
        for (int j = t; j < c; j += 32) s += d_bsum[j];
        #pragma unroll
        for (int o = 16; o; o >>= 1) s += __shfl_xor_sync(0xffffffffu, s, o);
        if (t == 0) s_off = s;
    }
    __syncthreads();
    int i = c * 1024 + t;
    if (i < n) {
        int rp = d_rowptr[i] + s_off;
        d_rowptr[i] = rp;
        d_cursor[i] = rp;
        float deg = (float)(d_cnt[i] + 1);   // +1 self loop
        d_dinv[i]   = rsqrtf(deg);
        d_invdeg[i] = 1.0f / deg;
    }
    if (i == 0) d_rowptr[n] = Etot;
}

__global__ void fill_csr_kernel(const int* __restrict__ src,
                                const int* __restrict__ dst, int E) {
    int i = blockIdx.x * blockDim.x + threadIdx.x;
    int e = i * 4;
    if (e + 3 < E) {
        int4 d = *(const int4*)(dst + e);
        int4 s = *(const int4*)(src + e);
        d_col[atomicAdd(&d_cursor[d.x], 1)] = s.x;
        d_col[atomicAdd(&d_cursor[d.y], 1)] = s.y;
        d_col[atomicAdd(&d_cursor[d.z], 1)] = s.z;
        d_col[atomicAdd(&d_cursor[d.w], 1)] = s.w;
    } else {
        for (; e < E; e++) {
            int p = atomicAdd(&d_cursor[dst[e]], 1);
            d_col[p] = src[e];
        }
    }
}

// ---------------- fused agg1 + GEMM1 + GEMM2: warp-specialized ---------------
// Persistent blocks (1/SM). Warps 0-3 produce: aggregate 64-row chunks into a
// double-buffered smem A tile (duplicated (a,a) layout). Warps 4-7 consume:
// G = relu(A@W1+b1)@W2 straight from smem (H staged in the consumed A buffer).
// Named barriers: FULL_s = 3+s, FREE_s = 1+s, count 256 (128 arrive +128 sync).
#define SU_STRIDE 132
#define BUF_FLOATS (64 * SU_STRIDE)
#define FUSED_SMEM_FLOATS (2 * BUF_FLOATS + 64 * 128 + 128 * 64)
#define FUSED_SMEM_BYTES  (FUSED_SMEM_FLOATS * 4)

__global__ __launch_bounds__(256, 1)
void fused_kernel(const float* __restrict__ W1, const float* __restrict__ b1,
                  const float* __restrict__ W2, int n) {
    extern __shared__ float smem[];
    float* buf0 = smem;
    float* buf1 = smem + BUF_FLOATS;
    float* sW1  = smem + 2 * BUF_FLOATS;   // paired layout [64][128]
    float* sW2  = sW1 + 64 * 128;          // [128][64]

    const int tid = threadIdx.x;
    const int nch = (n + 63) >> 6;

    // ---- weight preload (all 256 threads) ----
    for (int t = tid; t < 64 * 128; t += 256) {
        int k = t >> 7, c = t & 127;
        int txp = c & 15, m = c >> 4;
        int slot = (((m >> 1) * 16 + txp) << 1) + (m & 1);
        sW1[k * 128 + slot] = W1[t];
    }
    for (int t = tid; t < 128 * 16; t += 256)
        *(float4*)&sW2[t * 4] = *(const float4*)(W2 + t * 4);
    __syncthreads();

    if (tid < 128) {
        // ================= PRODUCER: aggregation ==========================
        const int warp = tid >> 5, lane = tid & 31;
        int it = 0;
        for (int ch = blockIdx.x; ch < nch; ch += gridDim.x, it++) {
            const int s = it & 1;
            if (it >= 2) NAMED_SYNC(1 + s, 256);       // wait buffer freed
            float* buf = s ? buf1 : buf0;
            const int rowBase = ch << 6;
            for (int rr = warp; rr < 64; rr += 4) {
                int r = rowBase + rr;
                if (r >= n) break;
                int beg = d_rowptr[r], end = d_rowptr[r + 1];
                float2 acc = make_float2(0.f, 0.f);
                int e = beg;
                int m4 = beg + ((end - beg) & ~3);
                for (; e < m4; e += 4) {          // unroll-4 for MLP
                    int s0 = d_col[e],     s1 = d_col[e + 1];
                    int s2 = d_col[e + 2], s3 = d_col[e + 3];
                    float w0 = d_dinv[s0], w1 = d_dinv[s1];
                    float w2 = d_dinv[s2], w3 = d_dinv[s3];
                    float2 x0 = *(const float2*)(d_x + (size_t)s0 * DIM + lane * 2);
                    float2 x1 = *(const float2*)(d_x + (size_t)s1 * DIM + lane * 2);
                    float2 x2 = *(const float2*)(d_x + (size_t)s2 * DIM + lane * 2);
                    float2 x3 = *(const float2*)(d_x + (size_t)s3 * DIM + lane * 2);
                    acc.x = fmaf(w0, x0.x, acc.x); acc.y = fmaf(w0, x0.y, acc.y);
                    acc.x = fmaf(w1, x1.x, acc.x); acc.y = fmaf(w1, x1.y, acc.y);
                    acc.x = fmaf(w2, x2.x, acc.x); acc.y = fmaf(w2, x2.y, acc.y);
                    acc.x = fmaf(w3, x3.x, acc.x); acc.y = fmaf(w3, x3.y, acc.y);
                }
                for (; e < end; e++) {
                    int sc = d_col[e];
                    float w = d_dinv[sc];
                    float2 xs = *(const float2*)(d_x + (size_t)sc * DIM + lane * 2);
                    acc.x = fmaf(w, xs.x, acc.x);
                    acc.y = fmaf(w, xs.y, acc.y);
                }
                float di = d_dinv[r], id = d_invdeg[r];
                float2 self = *(const float2*)(d_x + (size_t)r * DIM + lane * 2);
                float ox = di * acc.x + id * self.x;
                float oy = di * acc.y + id * self.y;
                // duplicated layout: dims (2*lane, 2*lane+1) -> (x,x,y,y)
                *(float4*)&buf[rr * SU_STRIDE + 4 * lane] = make_float4(ox, ox, oy, oy);
            }
            __threadfence_block();
            NAMED_ARRIVE(3 + s, 256);                   // signal buffer full
        }
    } else {
        // ================= CONSUMER: double GEMM ==========================
        const int c  = tid - 128;
        const int tx = c & 15, ty = c >> 4;
        const int r0 = ty * 8;

        float b1c[8];
        #pragma unroll
        for (int j = 0; j < 4; j++) {
            b1c[j * 2]     = b1[tx + 32 * j];
            b1c[j * 2 + 1] = b1[tx + 32 * j + 16];
        }

        int it = 0;
        for (int ch = blockIdx.x; ch < nch; ch += gridDim.x, it++) {
            const int s = it & 1;
            NAMED_SYNC(3 + s, 256);                     // wait buffer full
            float* buf = s ? buf1 : buf0;
            const int rowBase = ch << 6;

            // ---- stage 1: acc[i][j] = row r0+i, col pair (tx+32j, tx+32j+16)
            unsigned long long acc[8][4];
            #pragma unroll
            for (int i = 0; i < 8; i++)
                #pragma unroll
                for (int j = 0; j < 4; j++) acc[i][j] = 0ull;

            #pragma unroll 4
            for (int k = 0; k < 64; k++) {
                unsigned long long bd[4];
                #pragma unroll
                for (int j = 0; j < 4; j++)
                    bd[j] = *(const unsigned long long*)&sW1[k * 128 + ((j * 16 + tx) << 1)];
                #pragma unroll
                for (int i = 0; i < 8; i++) {
                    unsigned long long ad =
                        *(const unsigned long long*)&buf[(r0 + i) * SU_STRIDE + 2 * k];
                    #pragma unroll
                    for (int j = 0; j < 4; j++)
                        acc[i][j] = fma2(ad, bd[j], acc[i][j]);
                }
            }
            __syncwarp();   // same-ty readers (in this warp) done with A rows

            // ---- bias + relu + stage H into the same buffer ----
            #pragma unroll
            for (int i = 0; i < 8; i++) {
                int rr = (r0 + i) * SU_STRIDE;
                #pragma unroll
                for (int j = 0; j < 4; j++) {
                    float2 v = upk2(acc[i][j]);
                    int cc = tx + 32 * j;
                    buf[rr + cc]      = fmaxf(v.x + b1c[j * 2], 0.f);
                    buf[rr + cc + 16] = fmaxf(v.y + b1c[j * 2 + 1], 0.f);
                }
            }
            __syncwarp();   // H rows for this ty complete

            // ---- stage 2: acc2[i][j] = row r0+i, cols (4tx+2j, 4tx+2j+1) ----
            unsigned long long acc2[8][2];
            #pragma unroll
            for (int i = 0; i < 8; i++) { acc2[i][0] = 0ull; acc2[i][1] = 0ull; }

            #pragma unroll 4
            for (int k = 0; k < 128; k++) {
                unsigned long long bd0 = *(const unsigned long long*)&sW2[k * 64 + 4 * tx];
                unsigned long long bd1 = *(const unsigned long long*)&sW2[k * 64 + 4 * tx + 2];
                #pragma unroll
                for (int i = 0; i < 8; i++) {
                    float a = buf[(r0 + i) * SU_STRIDE + k];
                    unsigned long long ad = pk2(a, a);
                    acc2[i][0] = fma2(ad, bd0, acc2[i][0]);
                    acc2[i][1] = fma2(ad, bd1, acc2[i][1]);
                }
            }

            // ---- store G (float4, coalesced) ----
            #pragma unroll
            for (int i = 0; i < 8; i++) {
                int gr = rowBase + r0 + i;
                if (gr < n) {
                    float2 v0 = upk2(acc2[i][0]);
                    float2 v1 = upk2(acc2[i][1]);
                    *(float4*)&d_g[(size_t)gr * DIM + 4 * tx] =
                        make_float4(v0.x, v0.y, v1.x, v1.y);
                }
            }
            NAMED_ARRIVE(1 + s, 256);                   // release buffer
        }
    }
}

// ---------------- final: agg2 restricted to batch items + user dot ----------
__global__ void final_kernel(const int* __restrict__ u,
                             const int* __restrict__ it,
                             const float* __restrict__ user_emb,
                             const float* __restrict__ b2,
                             float* __restrict__ out, int B) {
    int gtid = blockIdx.x * blockDim.x + threadIdx.x;
    int w = gtid >> 5;
    int lane = gtid & 31;
    if (w >= B) return;

    int r = it[w];
    int beg = d_rowptr[r], end = d_rowptr[r + 1];
    float2 acc = make_float2(0.f, 0.f);
    for (int e = beg; e < end; e++) {
        int s = d_col[e];
        float wt = d_dinv[s];
        float2 gs = *(const float2*)(d_g + (size_t)s * DIM + lane * 2);
        acc.x = fmaf(wt, gs.x, acc.x);
        acc.y = fmaf(wt, gs.y, acc.y);
    }
    float di = d_dinv[r], id = d_invdeg[r];
    float2 gr = *(const float2*)(d_g + (size_t)r * DIM + lane * 2);
    float2 item = make_float2(di * acc.x + id * gr.x + b2[lane * 2 + 0],
                              di * acc.y + id * gr.y + b2[lane * 2 + 1]);

    int uu = u[w];
    float2 uv = *(const float2*)(user_emb + (size_t)uu * DIM + lane * 2);
    float ss = uv.x * uv.x + uv.y * uv.y;
    #pragma unroll
    for (int o = 16; o; o >>= 1) ss += __shfl_xor_sync(0xffffffffu, ss, o);
    float sc = fminf(1.0f, 1.0f / fmaxf(sqrtf(ss), 1e-12f));

    float dot = (uv.x * sc) * item.x + (uv.y * sc) * item.y;
    #pragma unroll
    for (int o = 16; o; o >>= 1) dot += __shfl_xor_sync(0xffffffffu, dot, o);

    if (lane == 0) out[w] = 1.0f / (1.0f + expf(-dot));
}

// ---------------- launch ----------------------------------------------------
extern "C" void kernel_launch(void* const* d_in, const int* in_sizes, int n_in,
                              void* d_out, int out_size) {
    const int*   u          = (const int*)d_in[0];
    const int*   it         = (const int*)d_in[1];
    const int*   edges      = (const int*)d_in[2];
    const float* user_emb   = (const float*)d_in[3];
    const float* entity_emb = (const float*)d_in[4];
    const float* W1         = (const float*)d_in[5];
    const float* b1         = (const float*)d_in[6];
    const float* W2         = (const float*)d_in[7];
    const float* b2         = (const float*)d_in[8];
    float*       out        = (float*)d_out;

    int B = in_sizes[0];
    int E = in_sizes[2] / 2;
    int n = in_sizes[4] / DIM;
    if (n > NCAP) n = NCAP;
    if (E > ECAP) E = ECAP;

    const int* src = edges;
    const int* dst = edges + E;

    const int T = 256;

    // renorm entities + zero degree counters (one kernel)
    renorm_zero_kernel<<<(n + 7) / 8, T>>>(entity_emb, n);

    // degree counts (int4)
    int e4 = (E + 3) / 4;
    count_deg_kernel<<<(e4 + T - 1) / T, T>>>(dst, E);

    // CSR build (scan_bsums folded into finalize)
    int nb = (n + 1023) / 1024;
    scan_chunk_kernel<<<nb, 1024>>>(n);
    finalize_rowptr_kernel<<<nb, 1024>>>(n, E);
    fill_csr_kernel<<<(e4 + T - 1) / T, T>>>(src, dst, E);

    // fused warp-specialized agg1 -> relu(A@W1+b1)@W2, persistent 1 block/SM
    cudaFuncSetAttribute(fused_kernel,
                         cudaFuncAttributeMaxDynamicSharedMemorySize,
                         FUSED_SMEM_BYTES);
    fused_kernel<<<152, 256, FUSED_SMEM_BYTES>>>(W1, b1, W2, n);

    // restricted layer-2 aggregation fused with user dot + sigmoid
    final_kernel<<<(B + 7) / 8, T>>>(u, it, user_emb, b2, out, B);
}

// round 11
// speedup vs baseline: 1.5678x; 1.5678x over previous
#include <cuda_runtime.h>
#include <math.h>

// Problem constants (fixed by the dataset)
#define NCAP 100000
#define ECAP 1600000
#define DIM  64
#define HID  128

// ---------------- scratch (device globals; no runtime allocation) ----------
static __device__ __align__(128) int   d_cnt[NCAP];
static __device__ __align__(128) int   d_rowptr[NCAP + 1];
static __device__ __align__(128) int   d_cursor[NCAP];
static __device__ __align__(128) int   d_bsum[256];
static __device__ __align__(128) int   d_col[ECAP];
static __device__ __align__(128) float d_dinv[NCAP];
static __device__ __align__(128) float d_invdeg[NCAP];
static __device__ __align__(128) float d_x[NCAP * DIM];      // renormed entity emb
static __device__ __align__(128) float d_agg1[NCAP * DIM];   // Ahat(x)
static __device__ __align__(128) float d_g[NCAP * DIM];      // relu(Ahat(x)W1+b1) @ W2

// ---------------- f32x2 packed math (Blackwell FFMA2) -----------------------
__device__ __forceinline__ unsigned long long fma2(unsigned long long a,
                                                   unsigned long long b,
                                                   unsigned long long c) {
    unsigned long long d;
    asm("fma.rn.f32x2 %0, %1, %2, %3;" : "=l"(d) : "l"(a), "l"(b), "l"(c));
    return d;
}
__device__ __forceinline__ float2 upk2(unsigned long long v) {
    unsigned int lo, hi;
    asm("mov.b64 {%0, %1}, %2;" : "=r"(lo), "=r"(hi) : "l"(v));
    return make_float2(__uint_as_float(lo), __uint_as_float(hi));
}

// ---------------- renorm entities + zero cnt (fused) -------------------------
__global__ void renorm_zero_kernel(const float* __restrict__ emb, int n) {
    int gtid = blockIdx.x * blockDim.x + threadIdx.x;
    if (gtid < n) d_cnt[gtid] = 0;
    int row = gtid >> 5;
    int lane = gtid & 31;
    if (row >= n) return;
    float2 v = *(const float2*)(emb + (size_t)row * DIM + lane * 2);
    float ss = v.x * v.x + v.y * v.y;
    #pragma unroll
    for (int o = 16; o; o >>= 1) ss += __shfl_xor_sync(0xffffffffu, ss, o);
    float nrm = sqrtf(ss);
    float sc = fminf(1.0f, 1.0f / fmaxf(nrm, 1e-12f));
    *(float2*)(d_x + (size_t)row * DIM + lane * 2) = make_float2(v.x * sc, v.y * sc);
}

// ---------------- degree counting (int4) -------------------------------------
__global__ void count_deg_kernel(const int* __restrict__ dst, int E) {
    int i = blockIdx.x * blockDim.x + threadIdx.x;
    int e = i * 4;
    if (e + 3 < E) {
        int4 d = *(const int4*)(dst + e);
        atomicAdd(&d_cnt[d.x], 1);
        atomicAdd(&d_cnt[d.y], 1);
        atomicAdd(&d_cnt[d.z], 1);
        atomicAdd(&d_cnt[d.w], 1);
    } else {
        for (; e < E; e++) atomicAdd(&d_cnt[dst[e]], 1);
    }
}

// ---------------- prefix sum (chunked) ---------------------------------------
__global__ void scan_chunk_kernel(int n) {
    __shared__ int s[1024];
    int t = threadIdx.x;
    int i = blockIdx.x * 1024 + t;
    int v = (i < n) ? d_cnt[i] : 0;
    s[t] = v;
    __syncthreads();
    for (int off = 1; off < 1024; off <<= 1) {
        int add = (t >= off) ? s[t - off] : 0;
        __syncthreads();
        s[t] += add;
        __syncthreads();
    }
    if (i < n) d_rowptr[i] = s[t] - v;   // chunk-local exclusive
    if (t == 1023) d_bsum[blockIdx.x] = s[1023];
}

// finalize with inline bsum prefix: block c adds sum(d_bsum[0..c))
__global__ void finalize_rowptr_kernel(int n, int Etot) {
    __shared__ int s_off;
    int c = blockIdx.x, t = threadIdx.x;
    if (t < 32) {
        int s = 0;
        for (int j = t; j < c; j += 32) s += d_bsum[j];
        #pragma unroll
        for (int o = 16; o; o >>= 1) s += __shfl_xor_sync(0xffffffffu, s, o);
        if (t == 0) s_off = s;
    }
    __syncthreads();
    int i = c * 1024 + t;
    if (i < n) {
        int rp = d_rowptr[i] + s_off;
        d_rowptr[i] = rp;
        d_cursor[i] = rp;
        float deg = (float)(d_cnt[i] + 1);   // +1 self loop
        d_dinv[i]   = rsqrtf(deg);
        d_invdeg[i] = 1.0f / deg;
    }
    if (i == 0) d_rowptr[n] = Etot;
}

__global__ void fill_csr_kernel(const int* __restrict__ src,
                                const int* __restrict__ dst, int E) {
    int i = blockIdx.x * blockDim.x + threadIdx.x;
    int e = i * 4;
    if (e + 3 < E) {
        int4 d = *(const int4*)(dst + e);
        int4 s = *(const int4*)(src + e);
        d_col[atomicAdd(&d_cursor[d.x], 1)] = s.x;
        d_col[atomicAdd(&d_cursor[d.y], 1)] = s.y;
        d_col[atomicAdd(&d_cursor[d.z], 1)] = s.z;
        d_col[atomicAdd(&d_cursor[d.w], 1)] = s.w;
    } else {
        for (; e < E; e++) {
            int p = atomicAdd(&d_cursor[dst[e]], 1);
            d_col[p] = src[e];
        }
    }
}

// ---------------- aggregation: d_agg1 = Ahat(d_x), unroll-4 ------------------
__global__ void aggregate1_kernel(int n) {
    int gtid = blockIdx.x * blockDim.x + threadIdx.x;
    int r = gtid >> 5;
    int lane = gtid & 31;
    if (r >= n) return;
    int beg = d_rowptr[r], end = d_rowptr[r + 1];
    float2 acc = make_float2(0.f, 0.f);
    int e = beg;
    int m4 = beg + ((end - beg) & ~3);
    for (; e < m4; e += 4) {
        int s0 = d_col[e],     s1 = d_col[e + 1];
        int s2 = d_col[e + 2], s3 = d_col[e + 3];
        float w0 = d_dinv[s0], w1 = d_dinv[s1];
        float w2 = d_dinv[s2], w3 = d_dinv[s3];
        float2 x0 = *(const float2*)(d_x + (size_t)s0 * DIM + lane * 2);
        float2 x1 = *(const float2*)(d_x + (size_t)s1 * DIM + lane * 2);
        float2 x2 = *(const float2*)(d_x + (size_t)s2 * DIM + lane * 2);
        float2 x3 = *(const float2*)(d_x + (size_t)s3 * DIM + lane * 2);
        acc.x = fmaf(w0, x0.x, acc.x); acc.y = fmaf(w0, x0.y, acc.y);
        acc.x = fmaf(w1, x1.x, acc.x); acc.y = fmaf(w1, x1.y, acc.y);
        acc.x = fmaf(w2, x2.x, acc.x); acc.y = fmaf(w2, x2.y, acc.y);
        acc.x = fmaf(w3, x3.x, acc.x); acc.y = fmaf(w3, x3.y, acc.y);
    }
    for (; e < end; e++) {
        int s = d_col[e];
        float w = d_dinv[s];
        float2 xs = *(const float2*)(d_x + (size_t)s * DIM + lane * 2);
        acc.x = fmaf(w, xs.x, acc.x);
        acc.y = fmaf(w, xs.y, acc.y);
    }
    float di = d_dinv[r], id = d_invdeg[r];
    float2 self = *(const float2*)(d_x + (size_t)r * DIM + lane * 2);
    float2 o = make_float2(di * acc.x + id * self.x,
                           di * acc.y + id * self.y);
    *(float2*)(d_agg1 + (size_t)r * DIM + lane * 2) = o;
}

// ---------------- fused GEMM1+GEMM2 with f32x2, dup-operand layout -----------
// Per block: rows [rowBase, rowBase+128)
//   stage 1: H = relu(A[128,64] @ W1[64,128] + b1)
//   stage 2: G = H[128,128] @ W2[128,64]
// A and H live in ONE union smem region in DUPLICATED layout: logical value v
// at col c stored at (2c, 2c+1) as (v,v) -> stage operands are single LDS.64
// broadcasts, no pack MOVs.
#define AD_STRIDE 132            // A-dup row stride (floats); 128 data + pad
#define HD_STRIDE 264            // H-dup row stride (floats); 256 data + pad
#define GU_FLOATS (128 * HD_STRIDE)
#define GEMM_SMEM_FLOATS (GU_FLOATS + 64 * 128 + 128 * 64)
#define GEMM_SMEM_BYTES  (GEMM_SMEM_FLOATS * 4)

__global__ __launch_bounds__(256, 1)
void gemm_fused_kernel(const float* __restrict__ W1, const float* __restrict__ b1,
                       const float* __restrict__ W2, int M) {
    extern __shared__ float smem[];
    float* sU  = smem;                   // union: A-dup [128][132] -> H-dup [128][264]
    float* sW1 = smem + GU_FLOATS;       // paired layout [64][128]
    float* sW2 = sW1 + 64 * 128;         // [128][64]

    const int tid = threadIdx.x;
    const int tx = tid & 15, ty = tid >> 4;
    const int r0 = ty * 8;
    const int rowBase = blockIdx.x * 128;

    // --- load W1 into pre-paired layout: pair (c, c+16) adjacent ---
    #pragma unroll
    for (int t = tid; t < 64 * 128; t += 256) {
        int k = t >> 7, c = t & 127;
        int txp = c & 15, m = c >> 4;
        int slot = (((m >> 1) * 16 + txp) << 1) + (m & 1);
        sW1[k * 128 + slot] = W1[t];
    }
    // --- load W2 (plain copy, float4; natural col pairs are adjacent) ---
    #pragma unroll
    for (int t = tid; t < 128 * 16; t += 256)
        *(float4*)&sW2[t * 4] = *(const float4*)(W2 + t * 4);

    // --- load A tile into duplicated layout ---
    #pragma unroll
    for (int t = tid; t < 128 * 16; t += 256) {
        int r = t >> 4, k4 = t & 15;
        float4 v = make_float4(0.f, 0.f, 0.f, 0.f);
        int gr = rowBase + r;
        if (gr < M) v = *(const float4*)(d_agg1 + (size_t)gr * DIM + k4 * 4);
        float* p = &sU[r * AD_STRIDE + k4 * 8];
        *(float4*)(p + 0) = make_float4(v.x, v.x, v.y, v.y);
        *(float4*)(p + 4) = make_float4(v.z, v.z, v.w, v.w);
    }
    __syncthreads();

    // ---- stage 1: acc[i][j] = row r0+i, col pair (tx+32j, tx+32j+16) ----
    unsigned long long acc[8][4];
    #pragma unroll
    for (int i = 0; i < 8; i++)
        #pragma unroll
        for (int j = 0; j < 4; j++) acc[i][j] = 0ull;

    #pragma unroll 4
    for (int k = 0; k < 64; k++) {
        unsigned long long bd[4];
        #pragma unroll
        for (int j = 0; j < 4; j++)
            bd[j] = *(const unsigned long long*)&sW1[k * 128 + ((j * 16 + tx) << 1)];
        #pragma unroll
        for (int i = 0; i < 8; i++) {
            unsigned long long ad =
                *(const unsigned long long*)&sU[(r0 + i) * AD_STRIDE + 2 * k];
            #pragma unroll
            for (int j = 0; j < 4; j++)
                acc[i][j] = fma2(ad, bd[j], acc[i][j]);
        }
    }
    __syncthreads();   // A-dup fully consumed; union region reused as H-dup

    // ---- bias + relu + write H in duplicated layout ----
    float b1c[8];
    #pragma unroll
    for (int j = 0; j < 4; j++) {
        b1c[j * 2]     = b1[tx + 32 * j];
        b1c[j * 2 + 1] = b1[tx + 32 * j + 16];
    }
    #pragma unroll
    for (int i = 0; i < 8; i++) {
        int rr = (r0 + i) * HD_STRIDE;
        #pragma unroll
        for (int j = 0; j < 4; j++) {
            float2 v = upk2(acc[i][j]);
            int cc = tx + 32 * j;
            float h0 = fmaxf(v.x + b1c[j * 2], 0.f);
            float h1 = fmaxf(v.y + b1c[j * 2 + 1], 0.f);
            *(float2*)&sU[rr + 2 * cc]        = make_float2(h0, h0);
            *(float2*)&sU[rr + 2 * (cc + 16)] = make_float2(h1, h1);
        }
    }
    __syncthreads();

    // ---- stage 2: acc2[i][j] = row r0+i, cols (4tx+2j, 4tx+2j+1) ----
    unsigned long long acc2[8][2];
    #pragma unroll
    for (int i = 0; i < 8; i++) { acc2[i][0] = 0ull; acc2[i][1] = 0ull; }

    #pragma unroll 4
    for (int k = 0; k < 128; k++) {
        unsigned long long bd0 = *(const unsigned long long*)&sW2[k * 64 + 4 * tx];
        unsigned long long bd1 = *(const unsigned long long*)&sW2[k * 64 + 4 * tx + 2];
        #pragma unroll
        for (int i = 0; i < 8; i++) {
            unsigned long long ad =
                *(const unsigned long long*)&sU[(r0 + i) * HD_STRIDE + 2 * k];
            acc2[i][0] = fma2(ad, bd0, acc2[i][0]);
            acc2[i][1] = fma2(ad, bd1, acc2[i][1]);
        }
    }

    // ---- store G (float4, coalesced) ----
    #pragma unroll
    for (int i = 0; i < 8; i++) {
        int gr = rowBase + r0 + i;
        if (gr < M) {
            float2 v0 = upk2(acc2[i][0]);
            float2 v1 = upk2(acc2[i][1]);
            *(float4*)&d_g[(size_t)gr * DIM + 4 * tx] =
                make_float4(v0.x, v0.y, v1.x, v1.y);
        }
    }
}

// ---------------- final: agg2 restricted to batch items + user dot ----------
__global__ void final_kernel(const int* __restrict__ u,
                             const int* __restrict__ it,
                             const float* __restrict__ user_emb,
                             const float* __restrict__ b2,
                             float* __restrict__ out, int B) {
    int gtid = blockIdx.x * blockDim.x + threadIdx.x;
    int w = gtid >> 5;
    int lane = gtid & 31;
    if (w >= B) return;

    int r = it[w];
    int beg = d_rowptr[r], end = d_rowptr[r + 1];
    float2 acc = make_float2(0.f, 0.f);
    for (int e = beg; e < end; e++) {
        int s = d_col[e];
        float wt = d_dinv[s];
        float2 gs = *(const float2*)(d_g + (size_t)s * DIM + lane * 2);
        acc.x = fmaf(wt, gs.x, acc.x);
        acc.y = fmaf(wt, gs.y, acc.y);
    }
    float di = d_dinv[r], id = d_invdeg[r];
    float2 gr = *(const float2*)(d_g + (size_t)r * DIM + lane * 2);
    float2 item = make_float2(di * acc.x + id * gr.x + b2[lane * 2 + 0],
                              di * acc.y + id * gr.y + b2[lane * 2 + 1]);

    int uu = u[w];
    float2 uv = *(const float2*)(user_emb + (size_t)uu * DIM + lane * 2);
    float ss = uv.x * uv.x + uv.y * uv.y;
    #pragma unroll
    for (int o = 16; o; o >>= 1) ss += __shfl_xor_sync(0xffffffffu, ss, o);
    float sc = fminf(1.0f, 1.0f / fmaxf(sqrtf(ss), 1e-12f));

    float dot = (uv.x * sc) * item.x + (uv.y * sc) * item.y;
    #pragma unroll
    for (int o = 16; o; o >>= 1) dot += __shfl_xor_sync(0xffffffffu, dot, o);

    if (lane == 0) out[w] = 1.0f / (1.0f + expf(-dot));
}

// ---------------- launch ----------------------------------------------------
extern "C" void kernel_launch(void* const* d_in, const int* in_sizes, int n_in,
                              void* d_out, int out_size) {
    const int*   u          = (const int*)d_in[0];
    const int*   it         = (const int*)d_in[1];
    const int*   edges      = (const int*)d_in[2];
    const float* user_emb   = (const float*)d_in[3];
    const float* entity_emb = (const float*)d_in[4];
    const float* W1         = (const float*)d_in[5];
    const float* b1         = (const float*)d_in[6];
    const float* W2         = (const float*)d_in[7];
    const float* b2         = (const float*)d_in[8];
    float*       out        = (float*)d_out;

    int B = in_sizes[0];
    int E = in_sizes[2] / 2;
    int n = in_sizes[4] / DIM;
    if (n > NCAP) n = NCAP;
    if (E > ECAP) E = ECAP;

    const int* src = edges;
    const int* dst = edges + E;

    const int T = 256;

    // renorm entities + zero degree counters (one kernel)
    renorm_zero_kernel<<<(n + 7) / 8, T>>>(entity_emb, n);

    // degree counts (int4)
    int e4 = (E + 3) / 4;
    count_deg_kernel<<<(e4 + T - 1) / T, T>>>(dst, E);

    // CSR build (scan_bsums folded into finalize)
    int nb = (n + 1023) / 1024;
    scan_chunk_kernel<<<nb, 1024>>>(n);
    finalize_rowptr_kernel<<<nb, 1024>>>(n, E);
    fill_csr_kernel<<<(e4 + T - 1) / T, T>>>(src, dst, E);

    // layer-1 aggregation in DIM space (full occupancy, unroll-4)
    aggregate1_kernel<<<(n + 7) / 8, T>>>(n);

    // fused g = relu(agg1@W1+b1) @ W2 with packed f32x2, dup-operand layout
    cudaFuncSetAttribute(gemm_fused_kernel,
                         cudaFuncAttributeMaxDynamicSharedMemorySize,
                         GEMM_SMEM_BYTES);
    int gblocks = (n + 127) / 128;
    gemm_fused_kernel<<<gblocks, 256, GEMM_SMEM_BYTES>>>(W1, b1, W2, n);

    // restricted layer-2 aggregation fused with user dot + sigmoid
    final_kernel<<<(B + 7) / 8, T>>>(u, it, user_emb, b2, out, B);
}

// round 12
// speedup vs baseline: 1.7899x; 1.1416x over previous
#include <cuda_runtime.h>
#include <math.h>

// Problem constants (fixed by the dataset)
#define NCAP 100000
#define ECAP 1600000
#define DIM  64
#define HID  128

// ---------------- scratch (device globals; no runtime allocation) ----------
static __device__ __align__(128) int   d_cnt[NCAP];
static __device__ __align__(128) int   d_rowptr[NCAP + 1];
static __device__ __align__(128) int   d_cursor[NCAP];
static __device__ __align__(128) int   d_bsum[256];
static __device__ __align__(128) int   d_col[ECAP];
static __device__ __align__(128) float d_dinv[NCAP];
static __device__ __align__(128) float d_invdeg[NCAP];
static __device__ __align__(128) float d_x[NCAP * DIM];      // renormed entity emb
static __device__ __align__(128) float d_agg1[NCAP * DIM];   // Ahat(x)
static __device__ __align__(128) float d_g[NCAP * DIM];      // relu(Ahat(x)W1+b1) @ W2

// ---------------- f32x2 packed math (Blackwell FFMA2) -----------------------
__device__ __forceinline__ unsigned long long pk2(float lo, float hi) {
    unsigned long long r;
    asm("mov.b64 %0, {%1, %2};" : "=l"(r) : "r"(__float_as_uint(lo)), "r"(__float_as_uint(hi)));
    return r;
}
__device__ __forceinline__ unsigned long long fma2(unsigned long long a,
                                                   unsigned long long b,
                                                   unsigned long long c) {
    unsigned long long d;
    asm("fma.rn.f32x2 %0, %1, %2, %3;" : "=l"(d) : "l"(a), "l"(b), "l"(c));
    return d;
}
__device__ __forceinline__ float2 upk2(unsigned long long v) {
    unsigned int lo, hi;
    asm("mov.b64 {%0, %1}, %2;" : "=r"(lo), "=r"(hi) : "l"(v));
    return make_float2(__uint_as_float(lo), __uint_as_float(hi));
}

// ---------------- renorm entities + zero cnt (fused) -------------------------
__global__ void renorm_zero_kernel(const float* __restrict__ emb, int n) {
    int gtid = blockIdx.x * blockDim.x + threadIdx.x;
    if (gtid < n) d_cnt[gtid] = 0;
    int row = gtid >> 5;
    int lane = gtid & 31;
    if (row >= n) return;
    float2 v = *(const float2*)(emb + (size_t)row * DIM + lane * 2);
    float ss = v.x * v.x + v.y * v.y;
    #pragma unroll
    for (int o = 16; o; o >>= 1) ss += __shfl_xor_sync(0xffffffffu, ss, o);
    float nrm = sqrtf(ss);
    float sc = fminf(1.0f, 1.0f / fmaxf(nrm, 1e-12f));
    *(float2*)(d_x + (size_t)row * DIM + lane * 2) = make_float2(v.x * sc, v.y * sc);
}

// ---------------- degree counting (int4) -------------------------------------
__global__ void count_deg_kernel(const int* __restrict__ dst, int E) {
    int i = blockIdx.x * blockDim.x + threadIdx.x;
    int e = i * 4;
    if (e + 3 < E) {
        int4 d = *(const int4*)(dst + e);
        atomicAdd(&d_cnt[d.x], 1);
        atomicAdd(&d_cnt[d.y], 1);
        atomicAdd(&d_cnt[d.z], 1);
        atomicAdd(&d_cnt[d.w], 1);
    } else {
        for (; e < E; e++) atomicAdd(&d_cnt[dst[e]], 1);
    }
}

// ---------------- prefix sum (chunked) ---------------------------------------
__global__ void scan_chunk_kernel(int n) {
    __shared__ int s[1024];
    int t = threadIdx.x;
    int i = blockIdx.x * 1024 + t;
    int v = (i < n) ? d_cnt[i] : 0;
    s[t] = v;
    __syncthreads();
    for (int off = 1; off < 1024; off <<= 1) {
        int add = (t >= off) ? s[t - off] : 0;
        __syncthreads();
        s[t] += add;
        __syncthreads();
    }
    if (i < n) d_rowptr[i] = s[t] - v;   // chunk-local exclusive
    if (t == 1023) d_bsum[blockIdx.x] = s[1023];
}

// finalize with inline bsum prefix: block c adds sum(d_bsum[0..c))
__global__ void finalize_rowptr_kernel(int n, int Etot) {
    __shared__ int s_off;
    int c = blockIdx.x, t = threadIdx.x;
    if (t < 32) {
        int s = 0;
        for (int j = t; j < c; j += 32) s += d_bsum[j];
        #pragma unroll
        for (int o = 16; o; o >>= 1) s += __shfl_xor_sync(0xffffffffu, s, o);
        if (t == 0) s_off = s;
    }
    __syncthreads();
    int i = c * 1024 + t;
    if (i < n) {
        int rp = d_rowptr[i] + s_off;
        d_rowptr[i] = rp;
        d_cursor[i] = rp;
        float deg = (float)(d_cnt[i] + 1);   // +1 self loop
        d_dinv[i]   = rsqrtf(deg);
        d_invdeg[i] = 1.0f / deg;
    }
    if (i == 0) d_rowptr[n] = Etot;
}

__global__ void fill_csr_kernel(const int* __restrict__ src,
                                const int* __restrict__ dst, int E) {
    int i = blockIdx.x * blockDim.x + threadIdx.x;
    int e = i * 4;
    if (e + 3 < E) {
        int4 d = *(const int4*)(dst + e);
        int4 s = *(const int4*)(src + e);
        d_col[atomicAdd(&d_cursor[d.x], 1)] = s.x;
        d_col[atomicAdd(&d_cursor[d.y], 1)] = s.y;
        d_col[atomicAdd(&d_cursor[d.z], 1)] = s.z;
        d_col[atomicAdd(&d_cursor[d.w], 1)] = s.w;
    } else {
        for (; e < E; e++) {
            int p = atomicAdd(&d_cursor[dst[e]], 1);
            d_col[p] = src[e];
        }
    }
}

// ---------------- aggregation: d_agg1 = Ahat(d_x) ---------------------------
// one warp per dst row; lane = float2 of the 64-dim feature (R8-exact)
__global__ void aggregate1_kernel(int n) {
    int gtid = blockIdx.x * blockDim.x + threadIdx.x;
    int r = gtid >> 5;
    int lane = gtid & 31;
    if (r >= n) return;
    int beg = d_rowptr[r], end = d_rowptr[r + 1];
    float2 acc = make_float2(0.f, 0.f);
    for (int e = beg; e < end; e++) {
        int s = d_col[e];
        float w = d_dinv[s];
        float2 xs = *(const float2*)(d_x + (size_t)s * DIM + lane * 2);
        acc.x = fmaf(w, xs.x, acc.x);
        acc.y = fmaf(w, xs.y, acc.y);
    }
    float di = d_dinv[r], id = d_invdeg[r];
    float2 self = *(const float2*)(d_x + (size_t)r * DIM + lane * 2);
    float2 o = make_float2(di * acc.x + id * self.x,
                           di * acc.y + id * self.y);
    *(float2*)(d_agg1 + (size_t)r * DIM + lane * 2) = o;
}

// ---------------- fused GEMM1+GEMM2 with f32x2 (R8-exact) --------------------
// Per block: rows [rowBase, rowBase+128)
//   stage 1: H = relu(A[128,64] @ W1[64,128] + b1)  -> smem (row-major, pad 132)
//   stage 2: G = H[128,128] @ W2[128,64]            -> d_g
// smem: sA[128][68] rowmajor | sW1 paired [64][128] | sW2 [128][64] | sH[128][132]
#define SA_STRIDE 68
#define SH_STRIDE 132
#define FUSED_SMEM_FLOATS (128 * SA_STRIDE + 64 * 128 + 128 * 64 + 128 * SH_STRIDE)
#define FUSED_SMEM_BYTES  (FUSED_SMEM_FLOATS * 4)

__global__ __launch_bounds__(256, 1)
void gemm_fused_kernel(const float* __restrict__ W1, const float* __restrict__ b1,
                       const float* __restrict__ W2, int M) {
    extern __shared__ float smem[];
    float* sA  = smem;                         // [128][SA_STRIDE]
    float* sW1 = sA  + 128 * SA_STRIDE;        // paired layout [64][128]
    float* sW2 = sW1 + 64 * 128;               // [128][64]
    float* sH  = sW2 + 128 * 64;               // [128][SH_STRIDE]

    const int tid = threadIdx.x;
    const int tx = tid & 15, ty = tid >> 4;
    const int r0 = ty * 8;
    const int rowBase = blockIdx.x * 128;

    // --- load A tile (row-major, float4, coalesced) ---
    #pragma unroll
    for (int t = tid; t < 128 * 16; t += 256) {
        int r = t >> 4, k4 = t & 15;
        float4 v = make_float4(0.f, 0.f, 0.f, 0.f);
        int gr = rowBase + r;
        if (gr < M) v = *(const float4*)(d_agg1 + (size_t)gr * DIM + k4 * 4);
        *(float4*)&sA[r * SA_STRIDE + k4 * 4] = v;
    }
    // --- load W1 into pre-paired layout: pair (c, c+16) adjacent ---
    // c = txp + 16*m  ->  slot = 2*((m>>1)*16 + txp) + (m&1)
    #pragma unroll
    for (int t = tid; t < 64 * 128; t += 256) {
        int k = t >> 7, c = t & 127;
        int txp = c & 15, m = c >> 4;
        int slot = (((m >> 1) * 16 + txp) << 1) + (m & 1);
        sW1[k * 128 + slot] = W1[t];
    }
    // --- load W2 (plain copy, float4) ---
    #pragma unroll
    for (int t = tid; t < 128 * 16; t += 256) {
        *(float4*)&sW2[t * 4] = *(const float4*)(W2 + t * 4);
    }
    __syncthreads();

    // ---- stage 1: acc[i][j] covers row r0+i, col pair (tx+32j, tx+32j+16) ----
    unsigned long long acc[8][4];
    #pragma unroll
    for (int i = 0; i < 8; i++)
        #pragma unroll
        for (int j = 0; j < 4; j++) acc[i][j] = 0ull;

    #pragma unroll 4
    for (int k = 0; k < 64; k++) {
        unsigned long long bd[4];
        #pragma unroll
        for (int j = 0; j < 4; j++)
            bd[j] = *(const unsigned long long*)&sW1[k * 128 + ((j * 16 + tx) << 1)];
        #pragma unroll
        for (int i = 0; i < 8; i++) {
            float a = sA[(r0 + i) * SA_STRIDE + k];
            unsigned long long ad = pk2(a, a);
            #pragma unroll
            for (int j = 0; j < 4; j++)
                acc[i][j] = fma2(ad, bd[j], acc[i][j]);
        }
    }

    // bias + relu + write H to smem (scalar writes, interleaved cols: <=2-way)
    float b1c[8];
    #pragma unroll
    for (int j = 0; j < 4; j++) {
        b1c[j * 2]     = b1[tx + 32 * j];
        b1c[j * 2 + 1] = b1[tx + 32 * j + 16];
    }
    #pragma unroll
    for (int i = 0; i < 8; i++) {
        int rr = (r0 + i) * SH_STRIDE;
        #pragma unroll
        for (int j = 0; j < 4; j++) {
            float2 v = upk2(acc[i][j]);
            int c = tx + 32 * j;
            sH[rr + c]      = fmaxf(v.x + b1c[j * 2], 0.f);
            sH[rr + c + 16] = fmaxf(v.y + b1c[j * 2 + 1], 0.f);
        }
    }
    __syncthreads();

    // ---- stage 2: acc2[i][j] covers row r0+i, cols (4tx+2j, 4tx+2j+1) ----
    unsigned long long acc2[8][2];
    #pragma unroll
    for (int i = 0; i < 8; i++) { acc2[i][0] = 0ull; acc2[i][1] = 0ull; }

    #pragma unroll 4
    for (int k = 0; k < 128; k++) {
        unsigned long long bd0 = *(const unsigned long long*)&sW2[k * 64 + 4 * tx];
        unsigned long long bd1 = *(const unsigned long long*)&sW2[k * 64 + 4 * tx + 2];
        #pragma unroll
        for (int i = 0; i < 8; i++) {
            float a = sH[(r0 + i) * SH_STRIDE + k];
            unsigned long long ad = pk2(a, a);
            acc2[i][0] = fma2(ad, bd0, acc2[i][0]);
            acc2[i][1] = fma2(ad, bd1, acc2[i][1]);
        }
    }

    // write G (float4, coalesced)
    #pragma unroll
    for (int i = 0; i < 8; i++) {
        int gr = rowBase + r0 + i;
        if (gr < M) {
            float2 v0 = upk2(acc2[i][0]);
            float2 v1 = upk2(acc2[i][1]);
            float4 o = make_float4(v0.x, v0.y, v1.x, v1.y);
            *(float4*)&d_g[(size_t)gr * DIM + 4 * tx] = o;
        }
    }
}

// ---------------- final: agg2 restricted to batch items + user dot ----------
__global__ void final_kernel(const int* __restrict__ u,
                             const int* __restrict__ it,
                             const float* __restrict__ user_emb,
                             const float* __restrict__ b2,
                             float* __restrict__ out, int B) {
    int gtid = blockIdx.x * blockDim.x + threadIdx.x;
    int w = gtid >> 5;
    int lane = gtid & 31;
    if (w >= B) return;

    int r = it[w];
    int beg = d_rowptr[r], end = d_rowptr[r + 1];
    float2 acc = make_float2(0.f, 0.f);
    for (int e = beg; e < end; e++) {
        int s = d_col[e];
        float wt = d_dinv[s];
        float2 gs = *(const float2*)(d_g + (size_t)s * DIM + lane * 2);
        acc.x = fmaf(wt, gs.x, acc.x);
        acc.y = fmaf(wt, gs.y, acc.y);
    }
    float di = d_dinv[r], id = d_invdeg[r];
    float2 gr = *(const float2*)(d_g + (size_t)r * DIM + lane * 2);
    float2 item = make_float2(di * acc.x + id * gr.x + b2[lane * 2 + 0],
                              di * acc.y + id * gr.y + b2[lane * 2 + 1]);

    int uu = u[w];
    float2 uv = *(const float2*)(user_emb + (size_t)uu * DIM + lane * 2);
    float ss = uv.x * uv.x + uv.y * uv.y;
    #pragma unroll
    for (int o = 16; o; o >>= 1) ss += __shfl_xor_sync(0xffffffffu, ss, o);
    float sc = fminf(1.0f, 1.0f / fmaxf(sqrtf(ss), 1e-12f));

    float dot = (uv.x * sc) * item.x + (uv.y * sc) * item.y;
    #pragma unroll
    for (int o = 16; o; o >>= 1) dot += __shfl_xor_sync(0xffffffffu, dot, o);

    if (lane == 0) out[w] = 1.0f / (1.0f + expf(-dot));
}

// ---------------- launch ----------------------------------------------------
extern "C" void kernel_launch(void* const* d_in, const int* in_sizes, int n_in,
                              void* d_out, int out_size) {
    const int*   u          = (const int*)d_in[0];
    const int*   it         = (const int*)d_in[1];
    const int*   edges      = (const int*)d_in[2];
    const float* user_emb   = (const float*)d_in[3];
    const float* entity_emb = (const float*)d_in[4];
    const float* W1         = (const float*)d_in[5];
    const float* b1         = (const float*)d_in[6];
    const float* W2         = (const float*)d_in[7];
    const float* b2         = (const float*)d_in[8];
    float*       out        = (float*)d_out;

    int B = in_sizes[0];
    int E = in_sizes[2] / 2;
    int n = in_sizes[4] / DIM;
    if (n > NCAP) n = NCAP;
    if (E > ECAP) E = ECAP;

    const int* src = edges;
    const int* dst = edges + E;

    const int T = 256;

    // renorm entities + zero degree counters (one kernel)
    renorm_zero_kernel<<<(n + 7) / 8, T>>>(entity_emb, n);

    // degree counts (int4)
    int e4 = (E + 3) / 4;
    count_deg_kernel<<<(e4 + T - 1) / T, T>>>(dst, E);

    // CSR build (scan_bsums folded into finalize)
    int nb = (n + 1023) / 1024;
    scan_chunk_kernel<<<nb, 1024>>>(n);
    finalize_rowptr_kernel<<<nb, 1024>>>(n, E);
    fill_csr_kernel<<<(e4 + T - 1) / T, T>>>(src, dst, E);

    // layer-1 aggregation in DIM space (full occupancy, R8-exact)
    aggregate1_kernel<<<(n + 7) / 8, T>>>(n);

    // fused g = relu(agg1@W1+b1) @ W2 with packed f32x2 (R8-exact)
    cudaFuncSetAttribute(gemm_fused_kernel,
                         cudaFuncAttributeMaxDynamicSharedMemorySize,
                         FUSED_SMEM_BYTES);
    int gblocks = (n + 127) / 128;
    gemm_fused_kernel<<<gblocks, 256, FUSED_SMEM_BYTES>>>(W1, b1, W2, n);

    // restricted layer-2 aggregation fused with user dot + sigmoid
    final_kernel<<<(B + 7) / 8, T>>>(u, it, user_emb, b2, out, B);
}

// round 13
// speedup vs baseline: 1.8276x; 1.0211x over previous
#include <cuda_runtime.h>
#include <cuda_fp16.h>
#include <math.h>

// Problem constants (fixed by the dataset)
#define NCAP 100000
#define ECAP 1600000
#define DIM  64
#define HID  128

// ---------------- scratch (device globals; no runtime allocation) ----------
static __device__ __align__(128) int   d_cnt[NCAP];
static __device__ __align__(128) int   d_rowptr[NCAP + 1];
static __device__ __align__(128) int   d_cursor[NCAP];
static __device__ __align__(128) int   d_bsum[256];
static __device__ __align__(128) int   d_col[ECAP];
static __device__ __align__(128) float d_dinv[NCAP];
static __device__ __align__(128) unsigned int d_xh[NCAP * 32]; // fp16x2 dinv*renorm(x)
static __device__ __align__(128) float d_agg1[NCAP * DIM];     // Ahat(x)
static __device__ __align__(128) float d_g[NCAP * DIM];        // dinv * (relu(Ahat(x)W1+b1) @ W2)

// ---------------- f32x2 packed math (Blackwell FFMA2) -----------------------
__device__ __forceinline__ unsigned long long pk2(float lo, float hi) {
    unsigned long long r;
    asm("mov.b64 %0, {%1, %2};" : "=l"(r) : "r"(__float_as_uint(lo)), "r"(__float_as_uint(hi)));
    return r;
}
__device__ __forceinline__ unsigned long long fma2(unsigned long long a,
                                                   unsigned long long b,
                                                   unsigned long long c) {
    unsigned long long d;
    asm("fma.rn.f32x2 %0, %1, %2, %3;" : "=l"(d) : "l"(a), "l"(b), "l"(c));
    return d;
}
__device__ __forceinline__ float2 upk2(unsigned long long v) {
    unsigned int lo, hi;
    asm("mov.b64 {%0, %1}, %2;" : "=r"(lo), "=r"(hi) : "l"(v));
    return make_float2(__uint_as_float(lo), __uint_as_float(hi));
}

// ---------------- zero degree counters ---------------------------------------
__global__ void zero_cnt_kernel(int n4) {
    int i = blockIdx.x * blockDim.x + threadIdx.x;
    if (i < n4) *(int4*)&d_cnt[i * 4] = make_int4(0, 0, 0, 0);
}

// ---------------- degree counting (int4) -------------------------------------
__global__ void count_deg_kernel(const int* __restrict__ dst, int E) {
    int i = blockIdx.x * blockDim.x + threadIdx.x;
    int e = i * 4;
    if (e + 3 < E) {
        int4 d = *(const int4*)(dst + e);
        atomicAdd(&d_cnt[d.x], 1);
        atomicAdd(&d_cnt[d.y], 1);
        atomicAdd(&d_cnt[d.z], 1);
        atomicAdd(&d_cnt[d.w], 1);
    } else {
        for (; e < E; e++) atomicAdd(&d_cnt[dst[e]], 1);
    }
}

// ---------------- prefix sum (chunked) ---------------------------------------
__global__ void scan_chunk_kernel(int n) {
    __shared__ int s[1024];
    int t = threadIdx.x;
    int i = blockIdx.x * 1024 + t;
    int v = (i < n) ? d_cnt[i] : 0;
    s[t] = v;
    __syncthreads();
    for (int off = 1; off < 1024; off <<= 1) {
        int add = (t >= off) ? s[t - off] : 0;
        __syncthreads();
        s[t] += add;
        __syncthreads();
    }
    if (i < n) d_rowptr[i] = s[t] - v;   // chunk-local exclusive
    if (t == 1023) d_bsum[blockIdx.x] = s[1023];
}

// finalize with inline bsum prefix: block c adds sum(d_bsum[0..c))
__global__ void finalize_rowptr_kernel(int n, int Etot) {
    __shared__ int s_off;
    int c = blockIdx.x, t = threadIdx.x;
    if (t < 32) {
        int s = 0;
        for (int j = t; j < c; j += 32) s += d_bsum[j];
        #pragma unroll
        for (int o = 16; o; o >>= 1) s += __shfl_xor_sync(0xffffffffu, s, o);
        if (t == 0) s_off = s;
    }
    __syncthreads();
    int i = c * 1024 + t;
    if (i < n) {
        int rp = d_rowptr[i] + s_off;
        d_rowptr[i] = rp;
        d_cursor[i] = rp;
        float deg = (float)(d_cnt[i] + 1);   // +1 self loop
        d_dinv[i] = rsqrtf(deg);
    }
    if (i == 0) d_rowptr[n] = Etot;
}

__global__ void fill_csr_kernel(const int* __restrict__ src,
                                const int* __restrict__ dst, int E) {
    int i = blockIdx.x * blockDim.x + threadIdx.x;
    int e = i * 4;
    if (e + 3 < E) {
        int4 d = *(const int4*)(dst + e);
        int4 s = *(const int4*)(src + e);
        d_col[atomicAdd(&d_cursor[d.x], 1)] = s.x;
        d_col[atomicAdd(&d_cursor[d.y], 1)] = s.y;
        d_col[atomicAdd(&d_cursor[d.z], 1)] = s.z;
        d_col[atomicAdd(&d_cursor[d.w], 1)] = s.w;
    } else {
        for (; e < E; e++) {
            int p = atomicAdd(&d_cursor[dst[e]], 1);
            d_col[p] = src[e];
        }
    }
}

// ---------------- renorm + premultiply by dinv, store fp16x2 -----------------
// x'[r] = dinv[r] * renorm(emb[r]);  one warp per row (needs d_dinv ready)
__global__ void renorm_premul_kernel(const float* __restrict__ emb, int n) {
    int gtid = blockIdx.x * blockDim.x + threadIdx.x;
    int row = gtid >> 5;
    int lane = gtid & 31;
    if (row >= n) return;
    float2 v = *(const float2*)(emb + (size_t)row * DIM + lane * 2);
    float ss = v.x * v.x + v.y * v.y;
    #pragma unroll
    for (int o = 16; o; o >>= 1) ss += __shfl_xor_sync(0xffffffffu, ss, o);
    float nrm = sqrtf(ss);
    float sc = fminf(1.0f, 1.0f / fmaxf(nrm, 1e-12f)) * d_dinv[row];
    __half2 h = __floats2half2_rn(v.x * sc, v.y * sc);
    d_xh[row * 32 + lane] = *(unsigned int*)&h;
}

// ---------------- aggregation: d_agg1 = Ahat(x) via premultiplied fp16 -------
// o[r] = dinv[r] * ( sum_{s in N(r)} x'[s]  +  x'[r] )
__global__ void aggregate1_kernel(int n) {
    int gtid = blockIdx.x * blockDim.x + threadIdx.x;
    int r = gtid >> 5;
    int lane = gtid & 31;
    if (r >= n) return;
    int beg = d_rowptr[r], end = d_rowptr[r + 1];
    float2 acc = make_float2(0.f, 0.f);
    for (int e = beg; e < end; e++) {
        int s = d_col[e];
        unsigned int hb = d_xh[s * 32 + lane];
        float2 xs = __half22float2(*(__half2*)&hb);
        acc.x += xs.x;
        acc.y += xs.y;
    }
    unsigned int hr = d_xh[r * 32 + lane];
    float2 self = __half22float2(*(__half2*)&hr);
    float di = d_dinv[r];
    float2 o = make_float2(di * (acc.x + self.x),
                           di * (acc.y + self.y));
    *(float2*)(d_agg1 + (size_t)r * DIM + lane * 2) = o;
}

// ---------------- fused GEMM1+GEMM2 with f32x2 (R12-exact + dinv epilogue) ---
// stage 1: H = relu(A[128,64] @ W1[64,128] + b1)  -> smem
// stage 2: G = dinv * (H[128,128] @ W2[128,64])   -> d_g (premultiplied)
#define SA_STRIDE 68
#define SH_STRIDE 132
#define FUSED_SMEM_FLOATS (128 * SA_STRIDE + 64 * 128 + 128 * 64 + 128 * SH_STRIDE)
#define FUSED_SMEM_BYTES  (FUSED_SMEM_FLOATS * 4)

__global__ __launch_bounds__(256, 1)
void gemm_fused_kernel(const float* __restrict__ W1, const float* __restrict__ b1,
                       const float* __restrict__ W2, int M) {
    extern __shared__ float smem[];
    float* sA  = smem;                         // [128][SA_STRIDE]
    float* sW1 = sA  + 128 * SA_STRIDE;        // paired layout [64][128]
    float* sW2 = sW1 + 64 * 128;               // [128][64]
    float* sH  = sW2 + 128 * 64;               // [128][SH_STRIDE]

    const int tid = threadIdx.x;
    const int tx = tid & 15, ty = tid >> 4;
    const int r0 = ty * 8;
    const int rowBase = blockIdx.x * 128;

    // --- load A tile (row-major, float4, coalesced) ---
    #pragma unroll
    for (int t = tid; t < 128 * 16; t += 256) {
        int r = t >> 4, k4 = t & 15;
        float4 v = make_float4(0.f, 0.f, 0.f, 0.f);
        int gr = rowBase + r;
        if (gr < M) v = *(const float4*)(d_agg1 + (size_t)gr * DIM + k4 * 4);
        *(float4*)&sA[r * SA_STRIDE + k4 * 4] = v;
    }
    // --- load W1 into pre-paired layout: pair (c, c+16) adjacent ---
    #pragma unroll
    for (int t = tid; t < 64 * 128; t += 256) {
        int k = t >> 7, c = t & 127;
        int txp = c & 15, m = c >> 4;
        int slot = (((m >> 1) * 16 + txp) << 1) + (m & 1);
        sW1[k * 128 + slot] = W1[t];
    }
    // --- load W2 (plain copy, float4) ---
    #pragma unroll
    for (int t = tid; t < 128 * 16; t += 256) {
        *(float4*)&sW2[t * 4] = *(const float4*)(W2 + t * 4);
    }
    __syncthreads();

    // ---- stage 1: acc[i][j] covers row r0+i, col pair (tx+32j, tx+32j+16) ----
    unsigned long long acc[8][4];
    #pragma unroll
    for (int i = 0; i < 8; i++)
        #pragma unroll
        for (int j = 0; j < 4; j++) acc[i][j] = 0ull;

    #pragma unroll 4
    for (int k = 0; k < 64; k++) {
        unsigned long long bd[4];
        #pragma unroll
        for (int j = 0; j < 4; j++)
            bd[j] = *(const unsigned long long*)&sW1[k * 128 + ((j * 16 + tx) << 1)];
        #pragma unroll
        for (int i = 0; i < 8; i++) {
            float a = sA[(r0 + i) * SA_STRIDE + k];
            unsigned long long ad = pk2(a, a);
            #pragma unroll
            for (int j = 0; j < 4; j++)
                acc[i][j] = fma2(ad, bd[j], acc[i][j]);
        }
    }

    // bias + relu + write H to smem
    float b1c[8];
    #pragma unroll
    for (int j = 0; j < 4; j++) {
        b1c[j * 2]     = b1[tx + 32 * j];
        b1c[j * 2 + 1] = b1[tx + 32 * j + 16];
    }
    #pragma unroll
    for (int i = 0; i < 8; i++) {
        int rr = (r0 + i) * SH_STRIDE;
        #pragma unroll
        for (int j = 0; j < 4; j++) {
            float2 v = upk2(acc[i][j]);
            int c = tx + 32 * j;
            sH[rr + c]      = fmaxf(v.x + b1c[j * 2], 0.f);
            sH[rr + c + 16] = fmaxf(v.y + b1c[j * 2 + 1], 0.f);
        }
    }
    __syncthreads();

    // ---- stage 2: acc2[i][j] covers row r0+i, cols (4tx+2j, 4tx+2j+1) ----
    unsigned long long acc2[8][2];
    #pragma unroll
    for (int i = 0; i < 8; i++) { acc2[i][0] = 0ull; acc2[i][1] = 0ull; }

    #pragma unroll 4
    for (int k = 0; k < 128; k++) {
        unsigned long long bd0 = *(const unsigned long long*)&sW2[k * 64 + 4 * tx];
        unsigned long long bd1 = *(const unsigned long long*)&sW2[k * 64 + 4 * tx + 2];
        #pragma unroll
        for (int i = 0; i < 8; i++) {
            float a = sH[(r0 + i) * SH_STRIDE + k];
            unsigned long long ad = pk2(a, a);
            acc2[i][0] = fma2(ad, bd0, acc2[i][0]);
            acc2[i][1] = fma2(ad, bd1, acc2[i][1]);
        }
    }

    // write G premultiplied by dinv (float4, coalesced)
    #pragma unroll
    for (int i = 0; i < 8; i++) {
        int gr = rowBase + r0 + i;
        if (gr < M) {
            float dv = d_dinv[gr];
            float2 v0 = upk2(acc2[i][0]);
            float2 v1 = upk2(acc2[i][1]);
            float4 o = make_float4(dv * v0.x, dv * v0.y, dv * v1.x, dv * v1.y);
            *(float4*)&d_g[(size_t)gr * DIM + 4 * tx] = o;
        }
    }
}

// ---------------- final: agg2 restricted to batch items + user dot ----------
// d_g holds g' = dinv*g:  item = dinv[r]*(sum g'[s] + g'[r]) + b2
__global__ void final_kernel(const int* __restrict__ u,
                             const int* __restrict__ it,
                             const float* __restrict__ user_emb,
                             const float* __restrict__ b2,
                             float* __restrict__ out, int B) {
    int gtid = blockIdx.x * blockDim.x + threadIdx.x;
    int w = gtid >> 5;
    int lane = gtid & 31;
    if (w >= B) return;

    int r = it[w];
    int beg = d_rowptr[r], end = d_rowptr[r + 1];
    float2 acc = make_float2(0.f, 0.f);
    for (int e = beg; e < end; e++) {
        int s = d_col[e];
        float2 gs = *(const float2*)(d_g + (size_t)s * DIM + lane * 2);
        acc.x += gs.x;
        acc.y += gs.y;
    }
    float di = d_dinv[r];
    float2 gr = *(const float2*)(d_g + (size_t)r * DIM + lane * 2);
    float2 item = make_float2(di * (acc.x + gr.x) + b2[lane * 2 + 0],
                              di * (acc.y + gr.y) + b2[lane * 2 + 1]);

    int uu = u[w];
    float2 uv = *(const float2*)(user_emb + (size_t)uu * DIM + lane * 2);
    float ss = uv.x * uv.x + uv.y * uv.y;
    #pragma unroll
    for (int o = 16; o; o >>= 1) ss += __shfl_xor_sync(0xffffffffu, ss, o);
    float sc = fminf(1.0f, 1.0f / fmaxf(sqrtf(ss), 1e-12f));

    float dot = (uv.x * sc) * item.x + (uv.y * sc) * item.y;
    #pragma unroll
    for (int o = 16; o; o >>= 1) dot += __shfl_xor_sync(0xffffffffu, dot, o);

    if (lane == 0) out[w] = 1.0f / (1.0f + expf(-dot));
}

// ---------------- launch ----------------------------------------------------
extern "C" void kernel_launch(void* const* d_in, const int* in_sizes, int n_in,
                              void* d_out, int out_size) {
    const int*   u          = (const int*)d_in[0];
    const int*   it         = (const int*)d_in[1];
    const int*   edges      = (const int*)d_in[2];
    const float* user_emb   = (const float*)d_in[3];
    const float* entity_emb = (const float*)d_in[4];
    const float* W1         = (const float*)d_in[5];
    const float* b1         = (const float*)d_in[6];
    const float* W2         = (const float*)d_in[7];
    const float* b2         = (const float*)d_in[8];
    float*       out        = (float*)d_out;

    int B = in_sizes[0];
    int E = in_sizes[2] / 2;
    int n = in_sizes[4] / DIM;
    if (n > NCAP) n = NCAP;
    if (E > ECAP) E = ECAP;

    const int* src = edges;
    const int* dst = edges + E;

    const int T = 256;

    // zero degree counters
    int n4 = (n + 3) / 4;
    zero_cnt_kernel<<<(n4 + T - 1) / T, T>>>(n4);

    // degree counts (int4)
    int e4 = (E + 3) / 4;
    count_deg_kernel<<<(e4 + T - 1) / T, T>>>(dst, E);

    // CSR build (scan_bsums folded into finalize; finalize computes dinv)
    int nb = (n + 1023) / 1024;
    scan_chunk_kernel<<<nb, 1024>>>(n);
    finalize_rowptr_kernel<<<nb, 1024>>>(n, E);

    // renorm + premultiply by dinv into fp16 table (needs dinv)
    renorm_premul_kernel<<<(n + 7) / 8, T>>>(entity_emb, n);

    fill_csr_kernel<<<(e4 + T - 1) / T, T>>>(src, dst, E);

    // layer-1 aggregation (fp16 gathers, premultiplied weights)
    aggregate1_kernel<<<(n + 7) / 8, T>>>(n);

    // fused g = dinv * (relu(agg1@W1+b1) @ W2) with packed f32x2
    cudaFuncSetAttribute(gemm_fused_kernel,
                         cudaFuncAttributeMaxDynamicSharedMemorySize,
                         FUSED_SMEM_BYTES);
    int gblocks = (n + 127) / 128;
    gemm_fused_kernel<<<gblocks, 256, FUSED_SMEM_BYTES>>>(W1, b1, W2, n);

    // restricted layer-2 aggregation fused with user dot + sigmoid
    final_kernel<<<(B + 7) / 8, T>>>(u, it, user_emb, b2, out, B);
}